// round 14
// baseline (speedup 1.0000x reference)
#include <cuda_runtime.h>
#include <cuda_fp16.h>
#include <cstdint>

// Problem dims (fixed per reference setup_inputs)
#define T_STEPS 64
#define BATCH   512
#define IN_DIM  784
#define HID     2048
#define OUT_DIM 10
#define M_TOT   (T_STEPS * BATCH)   // 32768

// fp16 2-way split: storage = 2 sections [hi | lo*2^11]
// GEMM = 3 logical products: hh (x1), hl (x2^-11), lh (x2^-11)
#define KSEC     832                // 784 padded to multiple of 64
#define KPACK    (2 * KSEC)         // 1664 halves per packed row
#define BK       64                 // K per pipeline chunk (halves)
#define SEC_CHK  (KSEC / BK)        // 13 chunks per section
#define NPROD    3
#define NCHK     (NPROD * SEC_CHK)  // 39 logical chunks
#define LO_SCALE (1.0f / 2048.0f)   // 2^-11, exact

// ---------------- scratch (device globals; no cudaMalloc allowed) -----------
__device__ float g_cur[(size_t)M_TOT * HID];          // 256 MiB
__device__ float g_woutT[HID * OUT_DIM];
__device__ __half g_A2[(size_t)M_TOT * KPACK];        // 104 MiB
__device__ __half g_B2[(size_t)HID * KPACK];          // 6.5 MiB

// ---------------- helpers ----------------------------------------------------
static __device__ __forceinline__ uint32_t s2u(const void* p) {
    uint32_t a;
    asm("{ .reg .u64 t; cvta.to.shared.u64 t, %1; cvt.u32.u64 %0, t; }"
        : "=r"(a) : "l"(p));
    return a;
}
static __device__ __forceinline__ void cp16(uint32_t dst, const void* src) {
    asm volatile("cp.async.cg.shared.global [%0], [%1], 16;"
                 :: "r"(dst), "l"(src) : "memory");
}
static __device__ __forceinline__ void ldmx4(uint32_t a, uint32_t* r) {
    asm volatile("ldmatrix.sync.aligned.m8n8.x4.shared.b16 {%0,%1,%2,%3}, [%4];"
                 : "=r"(r[0]), "=r"(r[1]), "=r"(r[2]), "=r"(r[3]) : "r"(a));
}
// named-barrier split ops (count = arrivals + syncs = 1024 for 512 threads)
static __device__ __forceinline__ void bar_arrive(int id) {
    asm volatile("bar.arrive %0, 1024;" :: "r"(id) : "memory");
}
static __device__ __forceinline__ void bar_sync(int id) {
    asm volatile("bar.sync %0, 1024;" :: "r"(id) : "memory");
}
// chained: c += a*b  (fp16 in, fp32 acc)
static __device__ __forceinline__ void mma16816(float* c,
        uint32_t a0, uint32_t a1, uint32_t a2, uint32_t a3,
        uint32_t b0, uint32_t b1) {
    asm volatile(
        "mma.sync.aligned.m16n8k16.row.col.f32.f16.f16.f32 "
        "{%0,%1,%2,%3}, {%4,%5,%6,%7}, {%8,%9}, {%0,%1,%2,%3};"
        : "+f"(c[0]), "+f"(c[1]), "+f"(c[2]), "+f"(c[3])
        : "r"(a0), "r"(a1), "r"(a2), "r"(a3), "r"(b0), "r"(b1));
}
// zero-start: d = a*b + 0
static __device__ __forceinline__ void mma16816_zc(float* d,
        uint32_t a0, uint32_t a1, uint32_t a2, uint32_t a3,
        uint32_t b0, uint32_t b1) {
    asm volatile(
        "mma.sync.aligned.m16n8k16.row.col.f32.f16.f16.f32 "
        "{%0,%1,%2,%3}, {%4,%5,%6,%7}, {%8,%9}, {%10,%11,%12,%13};"
        : "=f"(d[0]), "=f"(d[1]), "=f"(d[2]), "=f"(d[3])
        : "r"(a0), "r"(a1), "r"(a2), "r"(a3), "r"(b0), "r"(b1),
          "f"(0.0f), "f"(0.0f), "f"(0.0f), "f"(0.0f));
}
// swizzled byte offset: 128B rows, 8x 16B chunks, conflict-free
static __device__ __forceinline__ uint32_t swz(int r, int c) {
    return (uint32_t)(r * 128 + ((c ^ (r & 7)) << 4));
}

// ---------------- pack: fp32 -> [hi | lo*2^11] fp16, one thread per element --
__global__ void pack_kernel(const float* __restrict__ src,
                            __half* __restrict__ dst, int nrows) {
    int idx = blockIdx.x * blockDim.x + threadIdx.x;
    if (idx >= nrows * KSEC) return;
    int m = idx / KSEC;
    int k = idx - m * KSEC;
    float x = (k < IN_DIM) ? src[(size_t)m * IN_DIM + k] : 0.0f;
    __half hi = __float2half_rn(x);
    float r = (x - __half2float(hi)) * 2048.0f;   // scaled residual, exact *2^11
    __half lo = __float2half_rn(r);
    __half* row = dst + (size_t)m * KPACK;
    row[k]        = hi;
    row[KSEC + k] = lo;
}

// ---------------- tiny transpose: w_out [10,2048] -> [2048,10] --------------
__global__ void transpose_wout_kernel(const float* __restrict__ wout) {
    int i = blockIdx.x * blockDim.x + threadIdx.x;
    if (i < HID * OUT_DIM) {
        int o = i / HID;
        int h = i % HID;
        g_woutT[h * OUT_DIM + o] = wout[i];
    }
}

// ---------------- mma.sync fp16 GEMM: CUR = A' @ B'^T ------------------------
// BM=128, BN=128, BK=64. 512 threads = 16 warps (4x4), warp tile 32x32.
// Slack-1 pipeline: named barriers R[0..3] (stage data ready, ids 0-3) and
// F[0..3] (stage free, ids 4-7) replace the per-chunk __syncthreads. All
// barrier ops of chunk `it` precede its trailing mma, so a warp lagging in
// mma never blocks other warps' progress into the next chunk.
#define STAGES     4
#define STAGE_SZ   32768                 // 16KB A + 16KB B per stage
#define SMEM_TOT   (STAGES * STAGE_SZ)   // 128KB dynamic

static __device__ __forceinline__ void chunk_off(int i, int& kA, int& kB) {
    int p = i / SEC_CHK;
    int j = i - p * SEC_CHK;
    int sa, sb;
    switch (p) {
        case 0:  sa = 0; sb = 0; break;   // hh
        case 1:  sa = 0; sb = 1; break;   // hl
        default: sa = 1; sb = 0; break;   // lh
    }
    kA = sa * KSEC + j * BK;
    kB = sb * KSEC + j * BK;
}

__global__ __launch_bounds__(512, 1)
void gemm_kernel() {
    extern __shared__ char smem[];
    const uint32_t sb_base = s2u(smem);

    const int tid  = threadIdx.x;
    const int lane = tid & 31;
    const int wid  = tid >> 5;        // 0..15
    const int wm   = wid & 3;         // 4 groups -> M (32 rows each)
    const int wn   = wid >> 2;        // 4 groups -> N (32 cols each)
    const int bn   = blockIdx.x;      // 0..15
    const int bm   = blockIdx.y;      // 0..255

    const __half* gA = g_A2 + (size_t)(bm * 128) * KPACK;
    const __half* gB = g_B2 + (size_t)(bn * 128) * KPACK;

    // per-thread load mapping: 2 granules A + 2 granules B per stage
    const int ldr0 = tid >> 3,         ldc = tid & 7;  // g = tid
    const int ldr1 = (tid + 512) >> 3;                 // g = tid+512

    // compact ldmatrix addressing: addr = stage_base + row*128 + ksoff[ks]
    const int x7 = lane & 7;
    const int c0 = lane >> 4;         // 0 or 1
    uint32_t ksoff[4];
    #pragma unroll
    for (int ks = 0; ks < 4; ++ks)
        ksoff[ks] = (uint32_t)(((ks * 2 + c0) ^ x7) << 4);
    uint32_t rA[2], rB[2];
    #pragma unroll
    for (int mi = 0; mi < 2; ++mi)
        rA[mi] = (uint32_t)((wm * 32 + mi * 16 + (lane & 15)) * 128);
    #pragma unroll
    for (int nj = 0; nj < 2; ++nj)
        rB[nj] = (uint32_t)((wn * 32 + nj * 16 + (lane & 15)) * 128);

    float acc[2][4][4];               // master fp32 accumulators
    float cacc[2][4][4];              // chain accumulators
    #pragma unroll
    for (int mi = 0; mi < 2; ++mi)
        #pragma unroll
        for (int ni = 0; ni < 4; ++ni)
            #pragma unroll
            for (int q = 0; q < 4; ++q) acc[mi][ni][q] = 0.0f;

    // prologue: stages 0,1,2 (groups 0,1,2)
    #pragma unroll
    for (int p = 0; p < 3; ++p) {
        int kA, kB; chunk_off(p, kA, kB);
        uint32_t sa  = sb_base + p * STAGE_SZ;
        uint32_t sbb = sa + 16384;
        cp16(sa  + swz(ldr0, ldc), gA + (size_t)ldr0 * KPACK + kA + ldc * 8);
        cp16(sa  + swz(ldr1, ldc), gA + (size_t)ldr1 * KPACK + kA + ldc * 8);
        cp16(sbb + swz(ldr0, ldc), gB + (size_t)ldr0 * KPACK + kB + ldc * 8);
        cp16(sbb + swz(ldr1, ldc), gB + (size_t)ldr1 * KPACK + kB + ldc * 8);
        asm volatile("cp.async.commit_group;" ::: "memory");
    }
    // arm R[0]: own copies of group 0 landed
    asm volatile("cp.async.wait_group 2;" ::: "memory");
    bar_arrive(0);

    for (int it = 0; it < NCHK; ++it) {
        const int s = it & 3;

        // 1. stage-s data ready (arrivals posted by all threads last iter)
        bar_sync(s);

        const uint32_t baA = sb_base + s * STAGE_SZ;
        const uint32_t baB = baA + 16384;
        const uint32_t aA0 = baA + rA[0], aA1 = baA + rA[1];
        const uint32_t aB0 = baB + rB[0], aB1 = baB + rB[1];

        // chain policy: hh restarts every chunk; hl/lh chain whole section
        const bool is_hh  = (it < SEC_CHK);
        const bool zchunk = is_hh || (it == SEC_CHK) || (it == 2 * SEC_CHK);
        const bool drain  = is_hh || (it == 2 * SEC_CHK - 1) || (it == NCHK - 1);
        const float cs    = is_hh ? 1.0f : LO_SCALE;

        // 2. load all frags (double-buffered), interleave first 2 mma rounds;
        //    arrive F[s] immediately after the LAST ldmatrix of this stage.
        uint32_t a[2][2][4], b[2][2][4];
        ldmx4(aA0 + ksoff[0], a[0][0]);
        ldmx4(aA1 + ksoff[0], a[0][1]);
        ldmx4(aB0 + ksoff[0], b[0][0]);
        ldmx4(aB1 + ksoff[0], b[0][1]);
        ldmx4(aA0 + ksoff[1], a[1][0]);
        ldmx4(aA1 + ksoff[1], a[1][1]);
        ldmx4(aB0 + ksoff[1], b[1][0]);
        ldmx4(aB1 + ksoff[1], b[1][1]);

        // mma ks=0 (zero-start if chunk starts a chain)
        {
            const bool zstart = zchunk;
            #pragma unroll
            for (int mi = 0; mi < 2; ++mi)
                #pragma unroll
                for (int ni = 0; ni < 4; ++ni) {
                    int nj = ni >> 1, sub = ni & 1;
                    if (zstart)
                        mma16816_zc(cacc[mi][ni],
                                    a[0][mi][0], a[0][mi][1],
                                    a[0][mi][2], a[0][mi][3],
                                    b[0][nj][sub], b[0][nj][sub + 2]);
                    else
                        mma16816(cacc[mi][ni],
                                 a[0][mi][0], a[0][mi][1],
                                 a[0][mi][2], a[0][mi][3],
                                 b[0][nj][sub], b[0][nj][sub + 2]);
                }
        }
        // ldm ks=2 -> buf0
        ldmx4(aA0 + ksoff[2], a[0][0]);
        ldmx4(aA1 + ksoff[2], a[0][1]);
        ldmx4(aB0 + ksoff[2], b[0][0]);
        ldmx4(aB1 + ksoff[2], b[0][1]);
        // mma ks=1 (buf1)
        #pragma unroll
        for (int mi = 0; mi < 2; ++mi)
            #pragma unroll
            for (int ni = 0; ni < 4; ++ni) {
                int nj = ni >> 1, sub = ni & 1;
                mma16816(cacc[mi][ni],
                         a[1][mi][0], a[1][mi][1], a[1][mi][2], a[1][mi][3],
                         b[1][nj][sub], b[1][nj][sub + 2]);
            }
        // ldm ks=3 -> buf1 (LAST reads of stage s)
        ldmx4(aA0 + ksoff[3], a[1][0]);
        ldmx4(aA1 + ksoff[3], a[1][1]);
        ldmx4(aB0 + ksoff[3], b[1][0]);
        ldmx4(aB1 + ksoff[3], b[1][1]);

        // 3. done reading stage s (only if a future writer will sync it)
        if (it + 4 < NCHK) bar_arrive(4 + s);

        // 4. stage-free rendezvous + prefetch chunk it+3
        if (it + 3 < NCHK) {
            const int sw = (it + 3) & 3;
            if (it >= 1) bar_sync(4 + sw);
            int kA, kB; chunk_off(it + 3, kA, kB);
            uint32_t sa  = sb_base + sw * STAGE_SZ;
            uint32_t sbb = sa + 16384;
            cp16(sa  + swz(ldr0, ldc), gA + (size_t)ldr0 * KPACK + kA + ldc * 8);
            cp16(sa  + swz(ldr1, ldc), gA + (size_t)ldr1 * KPACK + kA + ldc * 8);
            cp16(sbb + swz(ldr0, ldc), gB + (size_t)ldr0 * KPACK + kB + ldc * 8);
            cp16(sbb + swz(ldr1, ldc), gB + (size_t)ldr1 * KPACK + kB + ldc * 8);
        }
        asm volatile("cp.async.commit_group;" ::: "memory");

        // 5. arm next iteration's ready barrier (own copies of group it+1 done)
        asm volatile("cp.async.wait_group 2;" ::: "memory");
        if (it + 1 < NCHK) bar_arrive((it + 1) & 3);

        // 6. remaining mma (ks=2 buf0, ks=3 buf1) — laggard-tolerant zone
        #pragma unroll
        for (int mi = 0; mi < 2; ++mi)
            #pragma unroll
            for (int ni = 0; ni < 4; ++ni) {
                int nj = ni >> 1, sub = ni & 1;
                mma16816(cacc[mi][ni],
                         a[0][mi][0], a[0][mi][1], a[0][mi][2], a[0][mi][3],
                         b[0][nj][sub], b[0][nj][sub + 2]);
            }
        #pragma unroll
        for (int mi = 0; mi < 2; ++mi)
            #pragma unroll
            for (int ni = 0; ni < 4; ++ni) {
                int nj = ni >> 1, sub = ni & 1;
                mma16816(cacc[mi][ni],
                         a[1][mi][0], a[1][mi][1], a[1][mi][2], a[1][mi][3],
                         b[1][nj][sub], b[1][nj][sub + 2]);
            }

        if (drain) {   // scaled FMA into masters
            #pragma unroll
            for (int mi = 0; mi < 2; ++mi)
                #pragma unroll
                for (int ni = 0; ni < 4; ++ni)
                    #pragma unroll
                    for (int q = 0; q < 4; ++q)
                        acc[mi][ni][q] = fmaf(cacc[mi][ni][q], cs,
                                              acc[mi][ni][q]);
        }
    }

    // epilogue: direct float2 stores
    #pragma unroll
    for (int mi = 0; mi < 2; ++mi) {
        int m = bm * 128 + wm * 32 + mi * 16 + (lane >> 2);
        #pragma unroll
        for (int ni = 0; ni < 4; ++ni) {
            int n = bn * 128 + wn * 32 + ni * 8 + (lane & 3) * 2;
            *(float2*)(g_cur + (size_t)m * HID + n) =
                make_float2(acc[mi][ni][0], acc[mi][ni][1]);
            *(float2*)(g_cur + (size_t)(m + 8) * HID + n) =
                make_float2(acc[mi][ni][2], acc[mi][ni][3]);
        }
    }
}

// ---------------- persistent per-batch scan (unchanged, validated R1) -------
#define SCAN_THREADS 256
#define UPT (HID / SCAN_THREADS)   // 8

__global__ __launch_bounds__(SCAN_THREADS, 2)
void scan_kernel(float* __restrict__ out) {
    const int b   = blockIdx.x;
    const int tid = threadIdx.x;

    float v1[UPT], i1[UPT];
    float w[UPT][OUT_DIM];
    #pragma unroll
    for (int j = 0; j < UPT; ++j) {
        v1[j] = 0.0f; i1[j] = 0.0f;
        int h = tid + j * SCAN_THREADS;
        #pragma unroll
        for (int o = 0; o < OUT_DIM; ++o) w[j][o] = g_woutT[h * OUT_DIM + o];
    }

    float vo = 0.0f, io = 0.0f, vmax = -1e30f;
    __shared__ float red[SCAN_THREADS / 32][OUT_DIM];

    for (int t = 0; t < T_STEPS; ++t) {
        const float* crow = g_cur + ((size_t)t * BATCH + b) * HID;

        float acc[OUT_DIM];
        #pragma unroll
        for (int o = 0; o < OUT_DIM; ++o) acc[o] = 0.0f;

        #pragma unroll
        for (int j = 0; j < UPT; ++j) {
            int h = tid + j * SCAN_THREADS;
            float c  = crow[h];
            float vd = v1[j] + 0.1f * (i1[j] - v1[j]);
            float id = i1[j] * 0.8f;
            float z  = (vd - 0.5f) > 0.0f ? 1.0f : 0.0f;
            v1[j] = (1.0f - z) * vd;
            i1[j] = id + c;
            if (z != 0.0f) {
                #pragma unroll
                for (int o = 0; o < OUT_DIM; ++o) acc[o] += w[j][o];
            }
        }

        #pragma unroll
        for (int o = 0; o < OUT_DIM; ++o) {
            #pragma unroll
            for (int s = 16; s > 0; s >>= 1)
                acc[o] += __shfl_xor_sync(0xffffffffu, acc[o], s);
        }
        int warp = tid >> 5, lane = tid & 31;
        if (lane == 0) {
            #pragma unroll
            for (int o = 0; o < OUT_DIM; ++o) red[warp][o] = acc[o];
        }
        __syncthreads();

        if (tid < OUT_DIM) {
            float s = 0.0f;
            #pragma unroll
            for (int wp = 0; wp < SCAN_THREADS / 32; ++wp) s += red[wp][tid];
            float vn = vo + 0.1f * (io - vo);
            io = io * 0.8f + s;
            vo = vn;
            vmax = fmaxf(vmax, vn);
        }
        __syncthreads();
    }

    if (tid < OUT_DIM) out[b * OUT_DIM + tid] = vmax;
}

// ---------------- launch ------------------------------------------------------
extern "C" void kernel_launch(void* const* d_in, const int* in_sizes, int n_in,
                              void* d_out, int out_size) {
    const float* x    = (const float*)d_in[0];  // [32768, 784]
    const float* w1   = (const float*)d_in[1];  // [2048, 784]
    const float* wout = (const float*)d_in[2];  // [10, 2048]
    float* out = (float*)d_out;                 // [512, 10]

    cudaFuncSetAttribute(gemm_kernel,
                         cudaFuncAttributeMaxDynamicSharedMemorySize, SMEM_TOT);

    transpose_wout_kernel<<<(HID * OUT_DIM + 255) / 256, 256>>>(wout);

    __half* a2; cudaGetSymbolAddress((void**)&a2, g_A2);
    __half* b2; cudaGetSymbolAddress((void**)&b2, g_B2);
    pack_kernel<<<((size_t)M_TOT * KSEC + 255) / 256, 256>>>(x, a2, M_TOT);
    pack_kernel<<<((size_t)HID * KSEC + 255) / 256, 256>>>(w1, b2, HID);

    dim3 ggrid(HID / 128, M_TOT / 128);  // (16, 256)
    gemm_kernel<<<ggrid, 512, SMEM_TOT>>>();

    scan_kernel<<<BATCH, SCAN_THREADS>>>(out);
}

// round 15
// speedup vs baseline: 1.1341x; 1.1341x over previous
#include <cuda_runtime.h>
#include <cuda_fp16.h>
#include <cstdint>

// Problem dims (fixed per reference setup_inputs)
#define T_STEPS 64
#define BATCH   512
#define IN_DIM  784
#define HID     2048
#define OUT_DIM 10
#define M_TOT   (T_STEPS * BATCH)   // 32768

// fp16 2-way split: storage = 2 sections [hi | lo*2^11]
// GEMM = 3 logical products: hh (x1), hl (x2^-11), lh (x2^-11)
#define KSEC     832                // 784 padded to multiple of 64
#define KPACK    (2 * KSEC)         // 1664 halves per packed row
#define BK       64                 // K per pipeline chunk (halves)
#define SEC_CHK  (KSEC / BK)        // 13 chunks per section
#define NPROD    3
#define NCHK     (NPROD * SEC_CHK)  // 39 logical chunks
#define LO_SCALE (1.0f / 2048.0f)   // 2^-11, exact

// ---------------- scratch (device globals; no cudaMalloc allowed) -----------
__device__ float g_cur[(size_t)M_TOT * HID];          // 256 MiB
__device__ float g_woutT[HID * OUT_DIM];
__device__ __half g_A2[(size_t)M_TOT * KPACK];        // 104 MiB
__device__ __half g_B2[(size_t)HID * KPACK];          // 6.5 MiB

// ---------------- helpers ----------------------------------------------------
static __device__ __forceinline__ uint32_t s2u(const void* p) {
    uint32_t a;
    asm("{ .reg .u64 t; cvta.to.shared.u64 t, %1; cvt.u32.u64 %0, t; }"
        : "=r"(a) : "l"(p));
    return a;
}
static __device__ __forceinline__ void cp16(uint32_t dst, const void* src) {
    asm volatile("cp.async.cg.shared.global [%0], [%1], 16;"
                 :: "r"(dst), "l"(src) : "memory");
}
static __device__ __forceinline__ void ldmx4(uint32_t a,
        uint32_t& r0, uint32_t& r1, uint32_t& r2, uint32_t& r3) {
    asm volatile("ldmatrix.sync.aligned.m8n8.x4.shared.b16 {%0,%1,%2,%3}, [%4];"
                 : "=r"(r0), "=r"(r1), "=r"(r2), "=r"(r3) : "r"(a));
}
// chained: c += a*b  (fp16 in, fp32 acc)
static __device__ __forceinline__ void mma16816(float* c,
        uint32_t a0, uint32_t a1, uint32_t a2, uint32_t a3,
        uint32_t b0, uint32_t b1) {
    asm volatile(
        "mma.sync.aligned.m16n8k16.row.col.f32.f16.f16.f32 "
        "{%0,%1,%2,%3}, {%4,%5,%6,%7}, {%8,%9}, {%0,%1,%2,%3};"
        : "+f"(c[0]), "+f"(c[1]), "+f"(c[2]), "+f"(c[3])
        : "r"(a0), "r"(a1), "r"(a2), "r"(a3), "r"(b0), "r"(b1));
}
// zero-start: d = a*b + 0
static __device__ __forceinline__ void mma16816_zc(float* d,
        uint32_t a0, uint32_t a1, uint32_t a2, uint32_t a3,
        uint32_t b0, uint32_t b1) {
    asm volatile(
        "mma.sync.aligned.m16n8k16.row.col.f32.f16.f16.f32 "
        "{%0,%1,%2,%3}, {%4,%5,%6,%7}, {%8,%9}, {%10,%11,%12,%13};"
        : "=f"(d[0]), "=f"(d[1]), "=f"(d[2]), "=f"(d[3])
        : "r"(a0), "r"(a1), "r"(a2), "r"(a3), "r"(b0), "r"(b1),
          "f"(0.0f), "f"(0.0f), "f"(0.0f), "f"(0.0f));
}
// swizzled byte offset: 128B rows, 8x 16B chunks, conflict-free
static __device__ __forceinline__ uint32_t swz(int r, int c) {
    return (uint32_t)(r * 128 + ((c ^ (r & 7)) << 4));
}

// ---------------- pack: fp32 -> [hi | lo*2^11] fp16, one thread per element --
__global__ void pack_kernel(const float* __restrict__ src,
                            __half* __restrict__ dst, int nrows) {
    int idx = blockIdx.x * blockDim.x + threadIdx.x;
    if (idx >= nrows * KSEC) return;
    int m = idx / KSEC;
    int k = idx - m * KSEC;
    float x = (k < IN_DIM) ? src[(size_t)m * IN_DIM + k] : 0.0f;
    __half hi = __float2half_rn(x);
    float r = (x - __half2float(hi)) * 2048.0f;   // scaled residual, exact *2^11
    __half lo = __float2half_rn(r);
    __half* row = dst + (size_t)m * KPACK;
    row[k]        = hi;
    row[KSEC + k] = lo;
}

// ---------------- tiny transpose: w_out [10,2048] -> [2048,10] --------------
__global__ void transpose_wout_kernel(const float* __restrict__ wout) {
    int i = blockIdx.x * blockDim.x + threadIdx.x;
    if (i < HID * OUT_DIM) {
        int o = i / HID;
        int h = i % HID;
        g_woutT[h * OUT_DIM + o] = wout[i];
    }
}

// ---------------- mma.sync fp16 GEMM: CUR = A' @ B'^T ------------------------
// BM=128, BN=128, BK=64. 512 threads = 16 warps (4x4), warp tile 32x32.
// R12 structure, but prefetch distance 2 + STAGES=4 lets us rendezvous only
// every SECOND chunk: at even it, wait_group 0 + __syncthreads publishes
// chunks it and it+1; odd chunks run barrier-free. Stage written at chunk it
// is (it+2)&3, last read at it-2 — separated by the even-it sync (both
// parities checked).
#define STAGES     4
#define STAGE_SZ   32768                 // 16KB A + 16KB B per stage
#define SMEM_TOT   (STAGES * STAGE_SZ)   // 128KB dynamic

static __device__ __forceinline__ void chunk_off(int i, int& kA, int& kB) {
    int p = i / SEC_CHK;
    int j = i - p * SEC_CHK;
    int sa, sb;
    switch (p) {
        case 0:  sa = 0; sb = 0; break;   // hh
        case 1:  sa = 0; sb = 1; break;   // hl
        default: sa = 1; sb = 0; break;   // lh
    }
    kA = sa * KSEC + j * BK;
    kB = sb * KSEC + j * BK;
}

__global__ __launch_bounds__(512, 1)
void gemm_kernel() {
    extern __shared__ char smem[];
    const uint32_t sb_base = s2u(smem);

    const int tid  = threadIdx.x;
    const int lane = tid & 31;
    const int wid  = tid >> 5;        // 0..15
    const int wm   = wid & 3;         // 4 groups -> M (32 rows each)
    const int wn   = wid >> 2;        // 4 groups -> N (32 cols each)
    const int bn   = blockIdx.x;      // 0..15
    const int bm   = blockIdx.y;      // 0..255

    const __half* gA = g_A2 + (size_t)(bm * 128) * KPACK;
    const __half* gB = g_B2 + (size_t)(bn * 128) * KPACK;

    // per-thread load mapping: 2 granules A + 2 granules B per stage
    const int ldr0 = tid >> 3,         ldc = tid & 7;  // g = tid
    const int ldr1 = (tid + 512) >> 3;                 // g = tid+512

    // per-thread ldmatrix offsets (within a stage): 4 k-steps of 16 halves
    uint32_t offA[2][4], offB[2][4];
    #pragma unroll
    for (int mi = 0; mi < 2; ++mi) {
        int r = wm * 32 + mi * 16 + (lane & 15);
        #pragma unroll
        for (int ks = 0; ks < 4; ++ks)
            offA[mi][ks] = swz(r, ks * 2 + (lane >> 4));
    }
    #pragma unroll
    for (int nj = 0; nj < 2; ++nj) {
        int r = wn * 32 + nj * 16 + (lane & 15);
        #pragma unroll
        for (int ks = 0; ks < 4; ++ks)
            offB[nj][ks] = swz(r, ks * 2 + (lane >> 4));
    }

    float acc[2][4][4];               // master fp32 accumulators
    float cacc[2][4][4];              // chain accumulators
    #pragma unroll
    for (int mi = 0; mi < 2; ++mi)
        #pragma unroll
        for (int ni = 0; ni < 4; ++ni)
            #pragma unroll
            for (int q = 0; q < 4; ++q) acc[mi][ni][q] = 0.0f;

    // prologue: chunks 0,1 (prefetch distance 2)
    #pragma unroll
    for (int p = 0; p < 2; ++p) {
        int kA, kB; chunk_off(p, kA, kB);
        uint32_t sa  = sb_base + p * STAGE_SZ;
        uint32_t sbb = sa + 16384;
        cp16(sa  + swz(ldr0, ldc), gA + (size_t)ldr0 * KPACK + kA + ldc * 8);
        cp16(sa  + swz(ldr1, ldc), gA + (size_t)ldr1 * KPACK + kA + ldc * 8);
        cp16(sbb + swz(ldr0, ldc), gB + (size_t)ldr0 * KPACK + kB + ldc * 8);
        cp16(sbb + swz(ldr1, ldc), gB + (size_t)ldr1 * KPACK + kB + ldc * 8);
        asm volatile("cp.async.commit_group;" ::: "memory");
    }

    for (int it = 0; it < NCHK; ++it) {
        if ((it & 1) == 0) {          // rendezvous every SECOND chunk
            asm volatile("cp.async.wait_group 0;" ::: "memory");
            __syncthreads();          // publishes chunks it and it+1
        }

        if (it + 2 < NCHK) {
            int s2 = (it + 2) % STAGES;
            int kA, kB; chunk_off(it + 2, kA, kB);
            uint32_t sa  = sb_base + s2 * STAGE_SZ;
            uint32_t sbb = sa + 16384;
            cp16(sa  + swz(ldr0, ldc), gA + (size_t)ldr0 * KPACK + kA + ldc * 8);
            cp16(sa  + swz(ldr1, ldc), gA + (size_t)ldr1 * KPACK + kA + ldc * 8);
            cp16(sbb + swz(ldr0, ldc), gB + (size_t)ldr0 * KPACK + kB + ldc * 8);
            cp16(sbb + swz(ldr1, ldc), gB + (size_t)ldr1 * KPACK + kB + ldc * 8);
            asm volatile("cp.async.commit_group;" ::: "memory");
        }

        const uint32_t baA = sb_base + (it % STAGES) * STAGE_SZ;
        const uint32_t baB = baA + 16384;

        // chain policy: hh restarts every chunk; hl/lh chain whole section
        const bool is_hh  = (it < SEC_CHK);
        const bool zchunk = is_hh || (it == SEC_CHK) || (it == 2 * SEC_CHK);
        const bool drain  = is_hh || (it == 2 * SEC_CHK - 1) || (it == NCHK - 1);
        const float cs    = is_hh ? 1.0f : LO_SCALE;

        #pragma unroll
        for (int ks = 0; ks < 4; ++ks) {
            uint32_t a[2][4];
            #pragma unroll
            for (int mi = 0; mi < 2; ++mi)
                ldmx4(baA + offA[mi][ks], a[mi][0], a[mi][1], a[mi][2], a[mi][3]);
            uint32_t b[2][4];
            #pragma unroll
            for (int nj = 0; nj < 2; ++nj)
                ldmx4(baB + offB[nj][ks], b[nj][0], b[nj][1], b[nj][2], b[nj][3]);

            const bool zstart = zchunk && (ks == 0);
            #pragma unroll
            for (int mi = 0; mi < 2; ++mi)
                #pragma unroll
                for (int ni = 0; ni < 4; ++ni) {
                    int nj = ni >> 1, sub = ni & 1;
                    if (zstart)
                        mma16816_zc(cacc[mi][ni],
                                    a[mi][0], a[mi][1], a[mi][2], a[mi][3],
                                    b[nj][sub], b[nj][sub + 2]);
                    else
                        mma16816(cacc[mi][ni],
                                 a[mi][0], a[mi][1], a[mi][2], a[mi][3],
                                 b[nj][sub], b[nj][sub + 2]);
                }
        }

        if (drain) {   // scaled FMA into masters
            #pragma unroll
            for (int mi = 0; mi < 2; ++mi)
                #pragma unroll
                for (int ni = 0; ni < 4; ++ni)
                    #pragma unroll
                    for (int q = 0; q < 4; ++q)
                        acc[mi][ni][q] = fmaf(cacc[mi][ni][q], cs,
                                              acc[mi][ni][q]);
        }
    }

    // epilogue: direct float2 stores
    #pragma unroll
    for (int mi = 0; mi < 2; ++mi) {
        int m = bm * 128 + wm * 32 + mi * 16 + (lane >> 2);
        #pragma unroll
        for (int ni = 0; ni < 4; ++ni) {
            int n = bn * 128 + wn * 32 + ni * 8 + (lane & 3) * 2;
            *(float2*)(g_cur + (size_t)m * HID + n) =
                make_float2(acc[mi][ni][0], acc[mi][ni][1]);
            *(float2*)(g_cur + (size_t)(m + 8) * HID + n) =
                make_float2(acc[mi][ni][2], acc[mi][ni][3]);
        }
    }
}

// ---------------- persistent per-batch scan (unchanged, validated R1) -------
#define SCAN_THREADS 256
#define UPT (HID / SCAN_THREADS)   // 8

__global__ __launch_bounds__(SCAN_THREADS, 2)
void scan_kernel(float* __restrict__ out) {
    const int b   = blockIdx.x;
    const int tid = threadIdx.x;

    float v1[UPT], i1[UPT];
    float w[UPT][OUT_DIM];
    #pragma unroll
    for (int j = 0; j < UPT; ++j) {
        v1[j] = 0.0f; i1[j] = 0.0f;
        int h = tid + j * SCAN_THREADS;
        #pragma unroll
        for (int o = 0; o < OUT_DIM; ++o) w[j][o] = g_woutT[h * OUT_DIM + o];
    }

    float vo = 0.0f, io = 0.0f, vmax = -1e30f;
    __shared__ float red[SCAN_THREADS / 32][OUT_DIM];

    for (int t = 0; t < T_STEPS; ++t) {
        const float* crow = g_cur + ((size_t)t * BATCH + b) * HID;

        float acc[OUT_DIM];
        #pragma unroll
        for (int o = 0; o < OUT_DIM; ++o) acc[o] = 0.0f;

        #pragma unroll
        for (int j = 0; j < UPT; ++j) {
            int h = tid + j * SCAN_THREADS;
            float c  = crow[h];
            float vd = v1[j] + 0.1f * (i1[j] - v1[j]);
            float id = i1[j] * 0.8f;
            float z  = (vd - 0.5f) > 0.0f ? 1.0f : 0.0f;
            v1[j] = (1.0f - z) * vd;
            i1[j] = id + c;
            if (z != 0.0f) {
                #pragma unroll
                for (int o = 0; o < OUT_DIM; ++o) acc[o] += w[j][o];
            }
        }

        #pragma unroll
        for (int o = 0; o < OUT_DIM; ++o) {
            #pragma unroll
            for (int s = 16; s > 0; s >>= 1)
                acc[o] += __shfl_xor_sync(0xffffffffu, acc[o], s);
        }
        int warp = tid >> 5, lane = tid & 31;
        if (lane == 0) {
            #pragma unroll
            for (int o = 0; o < OUT_DIM; ++o) red[warp][o] = acc[o];
        }
        __syncthreads();

        if (tid < OUT_DIM) {
            float s = 0.0f;
            #pragma unroll
            for (int wp = 0; wp < SCAN_THREADS / 32; ++wp) s += red[wp][tid];
            float vn = vo + 0.1f * (io - vo);
            io = io * 0.8f + s;
            vo = vn;
            vmax = fmaxf(vmax, vn);
        }
        __syncthreads();
    }

    if (tid < OUT_DIM) out[b * OUT_DIM + tid] = vmax;
}

// ---------------- launch ------------------------------------------------------
extern "C" void kernel_launch(void* const* d_in, const int* in_sizes, int n_in,
                              void* d_out, int out_size) {
    const float* x    = (const float*)d_in[0];  // [32768, 784]
    const float* w1   = (const float*)d_in[1];  // [2048, 784]
    const float* wout = (const float*)d_in[2];  // [10, 2048]
    float* out = (float*)d_out;                 // [512, 10]

    cudaFuncSetAttribute(gemm_kernel,
                         cudaFuncAttributeMaxDynamicSharedMemorySize, SMEM_TOT);

    transpose_wout_kernel<<<(HID * OUT_DIM + 255) / 256, 256>>>(wout);

    __half* a2; cudaGetSymbolAddress((void**)&a2, g_A2);
    __half* b2; cudaGetSymbolAddress((void**)&b2, g_B2);
    pack_kernel<<<((size_t)M_TOT * KSEC + 255) / 256, 256>>>(x, a2, M_TOT);
    pack_kernel<<<((size_t)HID * KSEC + 255) / 256, 256>>>(w1, b2, HID);

    dim3 ggrid(HID / 128, M_TOT / 128);  // (16, 256)
    gemm_kernel<<<ggrid, 512, SMEM_TOT>>>();

    scan_kernel<<<BATCH, SCAN_THREADS>>>(out);
}